// round 4
// baseline (speedup 1.0000x reference)
#include <cuda_runtime.h>
#include <math.h>

// Problem constants
#define Bb   16
#define Tt   32
#define Ss   128
#define Ff   3
#define Hh   256
#define NHh  8
#define DKk  32
#define TPp  4
#define BSr  2048            // B*S rows
#define KENC 528             // padded 3+256+256=515 -> 528
#define KDEC 768             // 256+256+256
#define NG   1024            // 4*H

// ---------------- device state / scratch (no allocations allowed) ----------------
__device__ float g_eh[BSr * Hh];
__device__ float g_ec[BSr * Hh];
__device__ float g_dh[BSr * Hh];
__device__ float g_q[BSr * Hh];
__device__ float g_k[BSr * Hh];
__device__ float g_v[BSr * Hh];
__device__ float g_code[BSr * Hh];
__device__ float g_zin[BSr * KDEC];     // concat input (enc uses ld=528, dec ld=768)
__device__ float g_z[BSr * NG];         // gate pre-activations
__device__ float g_wgpad[KENC * NG];    // zero-padded encoder gate weight

__device__ __forceinline__ float sigf(float x) { return 1.f / (1.f + expf(-x)); }

// ---------------- prep: reset state, build padded weight ----------------
__global__ void prep_kernel(const float* __restrict__ encWg)
{
    int idx = blockIdx.x * blockDim.x + threadIdx.x;
    int stride = gridDim.x * blockDim.x;
    for (int i = idx; i < BSr * Hh; i += stride) {
        g_eh[i] = 0.f; g_ec[i] = 0.f; g_dh[i] = 0.f;
    }
    for (int i = idx; i < KENC * NG; i += stride) {
        int r = i >> 10;                    // /1024
        g_wgpad[i] = (r < 515) ? encWg[i] : 0.f;
    }
}

// ---------------- tiled fp32 GEMM: C[2048,N] = A[2048,K] @ W[K,N] ----------------
// BM=BN=64, BK=16, 256 threads, 4x4 per-thread tile.
// mode 0: plain; mode 1: +bias; mode 2: sigmoid(x+bias)
__device__ __forceinline__ void gemm_body(
    const float* __restrict__ A, const float* __restrict__ W,
    float* __restrict__ C, int K, int N,
    const float* __restrict__ bias, int mode)
{
    __shared__ float As[16][68];   // transposed A tile, padded (row stride 272B, 16B-aligned)
    __shared__ float Bs[16][64];

    const int tid  = threadIdx.x;
    const int m0   = blockIdx.y * 64;
    const int n0   = blockIdx.x * 64;
    const int arow = tid >> 2;            // 0..63
    const int acol = (tid & 3) << 2;      // 0..12
    const int brow = tid >> 4;            // 0..15
    const int bcol = (tid & 15) << 2;     // 0..60
    const int tx   = tid & 15;
    const int ty   = tid >> 4;

    float acc[4][4];
    #pragma unroll
    for (int i = 0; i < 4; i++)
        #pragma unroll
        for (int j = 0; j < 4; j++) acc[i][j] = 0.f;

    const float* aptr = A + (long)(m0 + arow) * K + acol;
    const float* bptr = W + (long)brow * N + n0 + bcol;

    for (int k0 = 0; k0 < K; k0 += 16) {
        float4 av = *(const float4*)(aptr + k0);
        float4 bv = *(const float4*)(bptr + (long)k0 * N);
        As[acol + 0][arow] = av.x;
        As[acol + 1][arow] = av.y;
        As[acol + 2][arow] = av.z;
        As[acol + 3][arow] = av.w;
        *(float4*)&Bs[brow][bcol] = bv;
        __syncthreads();
        #pragma unroll
        for (int kk = 0; kk < 16; kk++) {
            float4 a4 = *(const float4*)&As[kk][ty << 2];
            float4 b4 = *(const float4*)&Bs[kk][tx << 2];
            float a[4] = {a4.x, a4.y, a4.z, a4.w};
            float b[4] = {b4.x, b4.y, b4.z, b4.w};
            #pragma unroll
            for (int i = 0; i < 4; i++)
                #pragma unroll
                for (int j = 0; j < 4; j++)
                    acc[i][j] = fmaf(a[i], b[j], acc[i][j]);
        }
        __syncthreads();
    }

    #pragma unroll
    for (int i = 0; i < 4; i++) {
        int m = m0 + (ty << 2) + i;
        float* cp = C + (long)m * N + n0 + (tx << 2);
        #pragma unroll
        for (int j = 0; j < 4; j++) {
            float v = acc[i][j];
            if (mode >= 1) v += bias[n0 + (tx << 2) + j];
            if (mode == 2) v = sigf(v);
            cp[j] = v;
        }
    }
}

__global__ void __launch_bounds__(256) gemm_kernel(
    const float* __restrict__ A, const float* __restrict__ W, float* __restrict__ C,
    int K, int N, const float* __restrict__ bias, int mode)
{
    gemm_body(A, W, C, K, N, bias, mode);
}

// QKV: three GEMMs sharing A, selected by blockIdx.z
__global__ void __launch_bounds__(256) gemm3_kernel(
    const float* __restrict__ A,
    const float* __restrict__ W0, const float* __restrict__ W1, const float* __restrict__ W2,
    float* __restrict__ C0, float* __restrict__ C1, float* __restrict__ C2)
{
    const float* W = (blockIdx.z == 0) ? W0 : ((blockIdx.z == 1) ? W1 : W2);
    float*       C = (blockIdx.z == 0) ? C0 : ((blockIdx.z == 1) ? C1 : C2);
    gemm_body(A, W, C, Hh, Hh, 0, 0);
}

// ---------------- attention + concat assembly ----------------
// Block of 256 handles 8 rows. Threads 0..63 do (row,head) attention, all
// threads then copy h (and x/code) into the concat buffer.
// Spatial trick: k/v of neighbor s' are rows of the precomputed h@Wk / h@Wv.
__global__ void __launch_bounds__(256) attn_kernel(
    const float* __restrict__ Q, const float* __restrict__ Km, const float* __restrict__ Vm,
    const float* __restrict__ Hs, const float* __restrict__ Xs,
    int xmode, int t, float* __restrict__ Z, int ldz, int xlen)
{
    const int row0 = blockIdx.x << 3;
    const int tid = threadIdx.x;

    if (tid < 64) {
        const int row  = row0 + (tid >> 3);
        const int head = tid & 7;
        const int b = row >> 7;
        const int s = row & 127;
        const float* qp = Q + (long)row * Hh + head * DKk;
        float qv[DKk];
        #pragma unroll
        for (int d = 0; d < DKk; d++) qv[d] = qp[d];

        const int offs[4] = {2, 1, -1, -2};   // after2, after1, before1, before2
        float sc[4];
        #pragma unroll
        for (int j = 0; j < 4; j++) {
            int sn = s + offs[j];
            float a = 0.f;
            if (sn >= 0 && sn < Ss) {
                const float* kp = Km + (long)(b * Ss + sn) * Hh + head * DKk;
                #pragma unroll
                for (int d = 0; d < DKk; d++) a = fmaf(qv[d], kp[d], a);
            }
            sc[j] = a * 0.17677669529663687f;   // 1/sqrt(32)
        }
        float mx = fmaxf(fmaxf(sc[0], sc[1]), fmaxf(sc[2], sc[3]));
        float e[4], ssum = 0.f;
        #pragma unroll
        for (int j = 0; j < 4; j++) { e[j] = expf(sc[j] - mx); ssum += e[j]; }
        float inv = 1.f / ssum;

        float ctx[DKk];
        #pragma unroll
        for (int d = 0; d < DKk; d++) ctx[d] = 0.f;
        #pragma unroll
        for (int j = 0; j < 4; j++) {
            int sn = s + offs[j];
            if (sn >= 0 && sn < Ss) {
                const float* vp = Vm + (long)(b * Ss + sn) * Hh + head * DKk;
                float w = e[j] * inv;
                #pragma unroll
                for (int d = 0; d < DKk; d++) ctx[d] = fmaf(w, vp[d], ctx[d]);
            }
        }
        float* zp = Z + (long)row * ldz + xlen + Hh + head * DKk;
        #pragma unroll
        for (int d = 0; d < DKk; d++) zp[d] = ctx[d];
    }

    // copy h into concat slot [xlen, xlen+H)
    for (int i = tid; i < 8 * Hh; i += 256) {
        int r = row0 + (i >> 8);
        int c = i & 255;
        Z[(long)r * ldz + xlen + c] = Hs[(long)r * Hh + c];
    }
    // copy x into concat slot [0, xlen)
    if (xmode == 0) {                      // encoder: x = input_data[b, t, s, :]
        for (int i = tid; i < 8 * Ff; i += 256) {
            int r = row0 + i / Ff;
            int f = i - (i / Ff) * Ff;
            int b = r >> 7, s = r & 127;
            Z[(long)r * ldz + f] = Xs[(((long)b * Tt + t) * Ss + s) * Ff + f];
        }
    } else {                               // decoder: x = code [row, H]
        for (int i = tid; i < 8 * Hh; i += 256) {
            int r = row0 + (i >> 8);
            int c = i & 255;
            Z[(long)r * ldz + c] = Xs[(long)r * Hh + c];
        }
    }
}

// ---------------- LSTM gate update ----------------
__global__ void __launch_bounds__(256) gates_kernel(
    const float* __restrict__ Zg, float* __restrict__ Hst, float* __restrict__ Cst, int dec)
{
    int idx = blockIdx.x * 256 + threadIdx.x;     // BSr*Hh threads
    int row = idx >> 8;
    int j = idx & 255;
    const float* zr = Zg + (long)row * NG;
    float zi = zr[j], zf = zr[256 + j], zg = zr[512 + j], zo = zr[768 + j];
    float c  = Cst[idx];
    float cn = sigf(zf) * c + sigf(zi) * tanhf(zg);
    float hn = sigf(zo) * tanhf(cn);
    if (!dec) Cst[idx] = cn;       // decoder discards c_new (c input aliases dh)
    Hst[idx] = hn;
}

// ---------------- output head: out/In/num assembly ----------------
__global__ void __launch_bounds__(128) out_kernel(
    const float* __restrict__ Dh, const float* __restrict__ outW,
    const float* __restrict__ outB, const float* __restrict__ inp,
    int t, float* __restrict__ Out)
{
    int b = blockIdx.x;
    int s = threadIdx.x;     // 128
    __shared__ float osh[Ss];
    const float* hp = Dh + (long)(b * Ss + s) * Hh;
    float acc = 0.f;
    #pragma unroll 8
    for (int d = 0; d < Hh; d++) acc = fmaf(hp[d], outW[d], acc);
    float o = acc + outB[0];
    osh[s] = o;
    __syncthreads();
    float In  = (s == 0) ? inp[(((long)b * Tt + (t + 1)) * Ss + 0) * Ff + 1] : osh[s - 1];
    float num = inp[(((long)b * Tt + t) * Ss + s) * Ff + 2] + In - o;
    if (t >= TPp) {
        float* op = Out + (((long)b * (Tt - 1 - TPp) + (t - TPp)) * Ss + s) * 3;
        op[0] = o; op[1] = In; op[2] = num;
    }
}

// ---------------- host launch ----------------
static float* symaddr(const void* sym)
{
    void* p = 0;
    cudaGetSymbolAddress(&p, sym);
    return (float*)p;
}

extern "C" void kernel_launch(void* const* d_in, const int* in_sizes, int n_in,
                              void* d_out, int out_size)
{
    const float* input = (const float*)d_in[0];
    const float* encWq = (const float*)d_in[1];
    const float* encWk = (const float*)d_in[2];
    const float* encWv = (const float*)d_in[3];
    const float* encWg = (const float*)d_in[4];
    const float* encbg = (const float*)d_in[5];
    const float* decWq = (const float*)d_in[6];
    const float* decWk = (const float*)d_in[7];
    const float* decWv = (const float*)d_in[8];
    const float* decWg = (const float*)d_in[9];
    const float* decbg = (const float*)d_in[10];
    const float* embW  = (const float*)d_in[11];
    const float* embb  = (const float*)d_in[12];
    const float* outW  = (const float*)d_in[13];
    const float* outB  = (const float*)d_in[14];
    float* out = (float*)d_out;

    float* p_eh   = symaddr(g_eh);
    float* p_ec   = symaddr(g_ec);
    float* p_dh   = symaddr(g_dh);
    float* p_q    = symaddr(g_q);
    float* p_k    = symaddr(g_k);
    float* p_v    = symaddr(g_v);
    float* p_code = symaddr(g_code);
    float* p_zin  = symaddr(g_zin);
    float* p_z    = symaddr(g_z);
    float* p_wgp  = symaddr(g_wgpad);

    prep_kernel<<<256, 256>>>(encWg);

    dim3 g3(Hh / 64, BSr / 64, 3);           // qkv
    dim3 gWg(NG / 64, BSr / 64);             // gate GEMMs
    dim3 gEmb(Hh / 64, BSr / 64);            // code GEMM

    for (int t = 0; t < Tt - 1; t++) {
        // ---- encoder cell ----
        gemm3_kernel<<<g3, 256>>>(p_eh, encWq, encWk, encWv, p_q, p_k, p_v);
        attn_kernel<<<BSr / 8, 256>>>(p_q, p_k, p_v, p_eh, input, 0, t, p_zin, KENC, Ff);
        gemm_kernel<<<gWg, 256>>>(p_zin, p_wgp, p_z, KENC, NG, encbg, 1);
        gates_kernel<<<BSr * Hh / 256, 256>>>(p_z, p_eh, p_ec, 0);
        // code = sigmoid(eh_new @ embW + embb)
        gemm_kernel<<<gEmb, 256>>>(p_eh, embW, p_code, Hh, Hh, embb, 2);
        // ---- decoder cell (h = c = old dh) ----
        gemm3_kernel<<<g3, 256>>>(p_dh, decWq, decWk, decWv, p_q, p_k, p_v);
        attn_kernel<<<BSr / 8, 256>>>(p_q, p_k, p_v, p_dh, p_code, 1, t, p_zin, KDEC, Hh);
        gemm_kernel<<<gWg, 256>>>(p_zin, decWg, p_z, KDEC, NG, decbg, 1);
        gates_kernel<<<BSr * Hh / 256, 256>>>(p_z, p_dh, p_dh, 1);
        // ---- output head ----
        out_kernel<<<Bb, Ss>>>(p_dh, outW, outB, input, t, out);
    }
}

// round 5
// speedup vs baseline: 1.2371x; 1.2371x over previous
#include <cuda_runtime.h>
#include <math.h>

// Problem constants
#define Bb   16
#define Tt   32
#define Ss   128
#define Ff   3
#define Hh   256
#define NHh  8
#define DKk  32
#define TPp  4
#define BSr  2048            // B*S rows
#define KENC 528             // padded 3+256+256=515 -> 528
#define KDEC 768             // 256+256+256
#define NG   1024            // 4*H

// ---------------- device state / scratch (no allocations allowed) ----------------
__device__ float g_eh[BSr * Hh];
__device__ float g_ec[BSr * Hh];
__device__ float g_dh[BSr * Hh];
__device__ float g_q[BSr * Hh];
__device__ float g_k[BSr * Hh];
__device__ float g_v[BSr * Hh];
__device__ float g_code[BSr * Hh];
__device__ float g_zin[BSr * KDEC];     // concat input (enc uses ld=528, dec ld=768)
__device__ float g_z[BSr * NG];         // gate pre-activations
__device__ float g_wgpad[KENC * NG];    // zero-padded encoder gate weight

__device__ __forceinline__ float sigf(float x) { return 1.f / (1.f + expf(-x)); }

// ---------------- prep: reset state, build padded weight ----------------
__global__ void prep_kernel(const float* __restrict__ encWg)
{
    int idx = blockIdx.x * blockDim.x + threadIdx.x;
    int stride = gridDim.x * blockDim.x;
    for (int i = idx; i < BSr * Hh; i += stride) {
        g_eh[i] = 0.f; g_ec[i] = 0.f; g_dh[i] = 0.f;
    }
    for (int i = idx; i < KENC * NG; i += stride) {
        int r = i >> 10;                    // /1024
        g_wgpad[i] = (r < 515) ? encWg[i] : 0.f;
    }
}

// ---------------- double-buffered fp32 GEMM: C[2048,N] = A[2048,K] @ W[K,N] -----
// BM=128, BN=64, BK=16, 256 threads, 8x4 per-thread microtile.
// mode 0: plain; mode 1: +bias; mode 2: sigmoid(x+bias)
__device__ __forceinline__ void gemm_body(
    const float* __restrict__ A, const float* __restrict__ W,
    float* __restrict__ C, int K, int N,
    const float* __restrict__ bias, int mode)
{
    // As stored transposed: As[stage][k][m], row stride 132 floats (=33 float4)
    __shared__ float As[2][16 * 132];
    __shared__ float Bs[2][16 * 64];

    const int tid = threadIdx.x;
    const int m0  = blockIdx.y * 128;
    const int n0  = blockIdx.x * 64;

    // global-load mapping
    const int ar  = tid >> 2;             // 0..63 (and +64)
    const int ac  = (tid & 3) << 2;       // 0,4,8,12
    const int br  = tid >> 4;             // 0..15
    const int bc  = (tid & 15) << 2;      // 0..60
    // compute mapping
    const int tx  = tid & 15;             // 0..15 -> 4 cols
    const int ty  = tid >> 4;             // 0..15 -> 8 rows

    const float* aptr0 = A + (long)(m0 + ar) * K + ac;
    const float* aptr1 = A + (long)(m0 + ar + 64) * K + ac;
    const float* bptr  = W + (long)br * N + n0 + bc;

    float acc[8][4];
    #pragma unroll
    for (int i = 0; i < 8; i++)
        #pragma unroll
        for (int j = 0; j < 4; j++) acc[i][j] = 0.f;

    const int nk = K >> 4;

    // preload tile 0
    float4 pa0 = *(const float4*)(aptr0);
    float4 pa1 = *(const float4*)(aptr1);
    float4 pb  = *(const float4*)(bptr);
    {
        float* as = As[0];
        as[(ac + 0) * 132 + ar] = pa0.x;
        as[(ac + 1) * 132 + ar] = pa0.y;
        as[(ac + 2) * 132 + ar] = pa0.z;
        as[(ac + 3) * 132 + ar] = pa0.w;
        as[(ac + 0) * 132 + ar + 64] = pa1.x;
        as[(ac + 1) * 132 + ar + 64] = pa1.y;
        as[(ac + 2) * 132 + ar + 64] = pa1.z;
        as[(ac + 3) * 132 + ar + 64] = pa1.w;
        *(float4*)&Bs[0][br * 64 + bc] = pb;
    }
    __syncthreads();

    for (int t = 0; t < nk; t++) {
        const int cur = t & 1;
        if (t + 1 < nk) {
            int k0 = (t + 1) << 4;
            pa0 = *(const float4*)(aptr0 + k0);
            pa1 = *(const float4*)(aptr1 + k0);
            pb  = *(const float4*)(bptr + (long)k0 * N);
        }
        const float4* asr = (const float4*)As[cur];
        const float4* bsr = (const float4*)Bs[cur];
        #pragma unroll
        for (int kk = 0; kk < 16; kk++) {
            float4 aA = asr[kk * 33 + ty * 2];
            float4 aB = asr[kk * 33 + ty * 2 + 1];
            float4 bb = bsr[kk * 16 + tx];
            float a[8] = {aA.x, aA.y, aA.z, aA.w, aB.x, aB.y, aB.z, aB.w};
            float b[4] = {bb.x, bb.y, bb.z, bb.w};
            #pragma unroll
            for (int i = 0; i < 8; i++)
                #pragma unroll
                for (int j = 0; j < 4; j++)
                    acc[i][j] = fmaf(a[i], b[j], acc[i][j]);
        }
        if (t + 1 < nk) {
            const int nxt = cur ^ 1;
            float* as = As[nxt];
            as[(ac + 0) * 132 + ar] = pa0.x;
            as[(ac + 1) * 132 + ar] = pa0.y;
            as[(ac + 2) * 132 + ar] = pa0.z;
            as[(ac + 3) * 132 + ar] = pa0.w;
            as[(ac + 0) * 132 + ar + 64] = pa1.x;
            as[(ac + 1) * 132 + ar + 64] = pa1.y;
            as[(ac + 2) * 132 + ar + 64] = pa1.z;
            as[(ac + 3) * 132 + ar + 64] = pa1.w;
            *(float4*)&Bs[nxt][br * 64 + bc] = pb;
        }
        __syncthreads();
    }

    // epilogue
    float4 bv = make_float4(0.f, 0.f, 0.f, 0.f);
    if (mode >= 1) bv = *(const float4*)(bias + n0 + (tx << 2));
    #pragma unroll
    for (int i = 0; i < 8; i++) {
        int m = m0 + ty * 8 + i;
        float4 v = make_float4(acc[i][0], acc[i][1], acc[i][2], acc[i][3]);
        if (mode >= 1) { v.x += bv.x; v.y += bv.y; v.z += bv.z; v.w += bv.w; }
        if (mode == 2) { v.x = sigf(v.x); v.y = sigf(v.y); v.z = sigf(v.z); v.w = sigf(v.w); }
        *(float4*)(C + (long)m * N + n0 + (tx << 2)) = v;
    }
}

__global__ void __launch_bounds__(256) gemm_kernel(
    const float* __restrict__ A, const float* __restrict__ W, float* __restrict__ C,
    int K, int N, const float* __restrict__ bias, int mode)
{
    gemm_body(A, W, C, K, N, bias, mode);
}

// QKV (+ optional emb as z==3): z=0..2 qkv from Ah; z=3 emb from Ae w/ sigmoid+bias
__global__ void __launch_bounds__(256) gemmqkv_kernel(
    const float* __restrict__ Ah, const float* __restrict__ Ae,
    const float* __restrict__ Wq, const float* __restrict__ Wk, const float* __restrict__ Wv,
    const float* __restrict__ We, const float* __restrict__ embb,
    float* __restrict__ Cq, float* __restrict__ Ck, float* __restrict__ Cv,
    float* __restrict__ Ce)
{
    int z = blockIdx.z;
    if (z == 0)      gemm_body(Ah, Wq, Cq, Hh, Hh, 0, 0);
    else if (z == 1) gemm_body(Ah, Wk, Ck, Hh, Hh, 0, 0);
    else if (z == 2) gemm_body(Ah, Wv, Cv, Hh, Hh, 0, 0);
    else             gemm_body(Ae, We, Ce, Hh, Hh, embb, 2);
}

// ---------------- attention + concat assembly ----------------
__global__ void __launch_bounds__(256) attn_kernel(
    const float* __restrict__ Q, const float* __restrict__ Km, const float* __restrict__ Vm,
    const float* __restrict__ Hs, const float* __restrict__ Xs,
    int xmode, int t, float* __restrict__ Z, int ldz, int xlen)
{
    const int row0 = blockIdx.x << 3;
    const int tid = threadIdx.x;

    if (tid < 64) {
        const int row  = row0 + (tid >> 3);
        const int head = tid & 7;
        const int b = row >> 7;
        const int s = row & 127;
        const float* qp = Q + (long)row * Hh + head * DKk;
        float qv[DKk];
        #pragma unroll
        for (int d = 0; d < DKk; d++) qv[d] = qp[d];

        const int offs[4] = {2, 1, -1, -2};
        float sc[4];
        #pragma unroll
        for (int j = 0; j < 4; j++) {
            int sn = s + offs[j];
            float a = 0.f;
            if (sn >= 0 && sn < Ss) {
                const float* kp = Km + (long)(b * Ss + sn) * Hh + head * DKk;
                #pragma unroll
                for (int d = 0; d < DKk; d++) a = fmaf(qv[d], kp[d], a);
            }
            sc[j] = a * 0.17677669529663687f;   // 1/sqrt(32)
        }
        float mx = fmaxf(fmaxf(sc[0], sc[1]), fmaxf(sc[2], sc[3]));
        float e[4], ssum = 0.f;
        #pragma unroll
        for (int j = 0; j < 4; j++) { e[j] = expf(sc[j] - mx); ssum += e[j]; }
        float inv = 1.f / ssum;

        float ctx[DKk];
        #pragma unroll
        for (int d = 0; d < DKk; d++) ctx[d] = 0.f;
        #pragma unroll
        for (int j = 0; j < 4; j++) {
            int sn = s + offs[j];
            if (sn >= 0 && sn < Ss) {
                const float* vp = Vm + (long)(b * Ss + sn) * Hh + head * DKk;
                float w = e[j] * inv;
                #pragma unroll
                for (int d = 0; d < DKk; d++) ctx[d] = fmaf(w, vp[d], ctx[d]);
            }
        }
        float* zp = Z + (long)row * ldz + xlen + Hh + head * DKk;
        #pragma unroll
        for (int d = 0; d < DKk; d++) zp[d] = ctx[d];
    }

    // copy h into concat slot [xlen, xlen+H)
    for (int i = tid; i < 8 * Hh; i += 256) {
        int r = row0 + (i >> 8);
        int c = i & 255;
        Z[(long)r * ldz + xlen + c] = Hs[(long)r * Hh + c];
    }
    // copy x into concat slot [0, xlen)
    if (xmode == 0) {                      // encoder: x = input_data[b, t, s, :]
        for (int i = tid; i < 8 * Ff; i += 256) {
            int r = row0 + i / Ff;
            int f = i - (i / Ff) * Ff;
            int b = r >> 7, s = r & 127;
            Z[(long)r * ldz + f] = Xs[(((long)b * Tt + t) * Ss + s) * Ff + f];
        }
    } else {                               // decoder: x = code [row, H]
        for (int i = tid; i < 8 * Hh; i += 256) {
            int r = row0 + (i >> 8);
            int c = i & 255;
            Z[(long)r * ldz + c] = Xs[(long)r * Hh + c];
        }
    }
}

// ---------------- LSTM gate update ----------------
__global__ void __launch_bounds__(256) gates_kernel(
    const float* __restrict__ Zg, float* __restrict__ Hst, float* __restrict__ Cst, int dec)
{
    int idx = blockIdx.x * 256 + threadIdx.x;     // BSr*Hh threads
    int row = idx >> 8;
    int j = idx & 255;
    const float* zr = Zg + (long)row * NG;
    float zi = zr[j], zf = zr[256 + j], zg = zr[512 + j], zo = zr[768 + j];
    float c  = Cst[idx];
    float cn = sigf(zf) * c + sigf(zi) * tanhf(zg);
    float hn = sigf(zo) * tanhf(cn);
    if (!dec) Cst[idx] = cn;       // decoder discards c_new (c input aliases dh)
    Hst[idx] = hn;
}

// ---------------- output head: out/In/num assembly ----------------
__global__ void __launch_bounds__(128) out_kernel(
    const float* __restrict__ Dh, const float* __restrict__ outW,
    const float* __restrict__ outB, const float* __restrict__ inp,
    int t, float* __restrict__ Out)
{
    int b = blockIdx.x;
    int s = threadIdx.x;     // 128
    __shared__ float osh[Ss];
    const float* hp = Dh + (long)(b * Ss + s) * Hh;
    float acc = 0.f;
    #pragma unroll 8
    for (int d = 0; d < Hh; d++) acc = fmaf(hp[d], outW[d], acc);
    float o = acc + outB[0];
    osh[s] = o;
    __syncthreads();
    float In  = (s == 0) ? inp[(((long)b * Tt + (t + 1)) * Ss + 0) * Ff + 1] : osh[s - 1];
    float num = inp[(((long)b * Tt + t) * Ss + s) * Ff + 2] + In - o;
    if (t >= TPp) {
        float* op = Out + (((long)b * (Tt - 1 - TPp) + (t - TPp)) * Ss + s) * 3;
        op[0] = o; op[1] = In; op[2] = num;
    }
}

// ---------------- host launch ----------------
static float* symaddr(const void* sym)
{
    void* p = 0;
    cudaGetSymbolAddress(&p, sym);
    return (float*)p;
}

extern "C" void kernel_launch(void* const* d_in, const int* in_sizes, int n_in,
                              void* d_out, int out_size)
{
    const float* input = (const float*)d_in[0];
    const float* encWq = (const float*)d_in[1];
    const float* encWk = (const float*)d_in[2];
    const float* encWv = (const float*)d_in[3];
    const float* encWg = (const float*)d_in[4];
    const float* encbg = (const float*)d_in[5];
    const float* decWq = (const float*)d_in[6];
    const float* decWk = (const float*)d_in[7];
    const float* decWv = (const float*)d_in[8];
    const float* decWg = (const float*)d_in[9];
    const float* decbg = (const float*)d_in[10];
    const float* embW  = (const float*)d_in[11];
    const float* embb  = (const float*)d_in[12];
    const float* outW  = (const float*)d_in[13];
    const float* outB  = (const float*)d_in[14];
    float* out = (float*)d_out;

    float* p_eh   = symaddr(g_eh);
    float* p_ec   = symaddr(g_ec);
    float* p_dh   = symaddr(g_dh);
    float* p_q    = symaddr(g_q);
    float* p_k    = symaddr(g_k);
    float* p_v    = symaddr(g_v);
    float* p_code = symaddr(g_code);
    float* p_zin  = symaddr(g_zin);
    float* p_z    = symaddr(g_z);
    float* p_wgp  = symaddr(g_wgpad);

    prep_kernel<<<256, 256>>>(encWg);

    dim3 gQKV3(Hh / 64, BSr / 128, 3);        // enc qkv
    dim3 gQKV4(Hh / 64, BSr / 128, 4);        // dec qkv + emb
    dim3 gWg(NG / 64, BSr / 128);             // gate GEMMs

    for (int t = 0; t < Tt - 1; t++) {
        // ---- encoder cell ----
        gemmqkv_kernel<<<gQKV3, 256>>>(p_eh, p_eh, encWq, encWk, encWv, embW, embb,
                                       p_q, p_k, p_v, p_code);
        attn_kernel<<<BSr / 8, 256>>>(p_q, p_k, p_v, p_eh, input, 0, t, p_zin, KENC, Ff);
        gemm_kernel<<<gWg, 256>>>(p_zin, p_wgp, p_z, KENC, NG, encbg, 1);
        gates_kernel<<<BSr * Hh / 256, 256>>>(p_z, p_eh, p_ec, 0);
        // ---- dec qkv (from old dh) + emb code (from new eh), one launch ----
        gemmqkv_kernel<<<gQKV4, 256>>>(p_dh, p_eh, decWq, decWk, decWv, embW, embb,
                                       p_q, p_k, p_v, p_code);
        attn_kernel<<<BSr / 8, 256>>>(p_q, p_k, p_v, p_dh, p_code, 1, t, p_zin, KDEC, Hh);
        gemm_kernel<<<gWg, 256>>>(p_zin, decWg, p_z, KDEC, NG, decbg, 1);
        gates_kernel<<<BSr * Hh / 256, 256>>>(p_z, p_dh, p_dh, 1);
        // ---- output head ----
        out_kernel<<<Bb, Ss>>>(p_dh, outW, outB, input, t, out);
    }
}